// round 6
// baseline (speedup 1.0000x reference)
#include <cuda_runtime.h>

// QCNN_58025008169535
// x: [32,128,128,3] f32, w: [4,4,3] f32 -> out: [32, 127*127, 4] f32

#define DIM 16
#define NL 4
#define NQ 4

static constexpr int Bc = 32, Hc = 128, Wc = 128;
static constexpr int PHc = Hc - 1, PWc = Wc - 1;
static constexpr int Pc = PHc * PWc;          // 16129
static constexpr int TOTALc = Bc * Pc;        // 516128
static constexpr int HALFc = TOTALc / 2;      // 258064

typedef unsigned long long ull;

// Packed U, column-major [k][s]: (re,re) and (-im,im) of U[s][k]
__device__ ulonglong2 g_Upk[DIM * DIM];

__device__ __forceinline__ float2 cmul(float2 a, float2 b) {
    return make_float2(fmaf(a.x, b.x, -a.y * b.y), fmaf(a.x, b.y, a.y * b.x));
}
__device__ __forceinline__ float2 cadd(float2 a, float2 b) {
    return make_float2(a.x + b.x, a.y + b.y);
}
__device__ __forceinline__ ull pk2(float lo, float hi) {
    ull r; asm("mov.b64 %0, {%1,%2};" : "=l"(r) : "f"(lo), "f"(hi)); return r;
}
__device__ __forceinline__ void upk2(ull v, float& lo, float& hi) {
    asm("mov.b64 {%0,%1}, %2;" : "=f"(lo), "=f"(hi) : "l"(v));
}
__device__ __forceinline__ ull ffma2(ull a, ull b, ull c) {
    ull d; asm("fma.rn.f32x2 %0, %1, %2, %3;" : "=l"(d) : "l"(a), "l"(b), "l"(c));
    return d;
}

// ---------------------------------------------------------------------------
// Kernel 1 (256 threads): build the variational unitary in parallel.
// ---------------------------------------------------------------------------
__global__ void k_build_U(const float* __restrict__ w) {
    __shared__ float2 sg[16][4];         // gate (h*4+q): u00,u01,u10,u11
    __shared__ float2 sM[4][DIM][DIM];   // layer matrices (CZ folded)
    __shared__ float2 sT[2][DIM][DIM];

    int tid = threadIdx.x;

    if (tid < 16) {
        float wx = w[tid * 3 + 0];
        float wy = w[tid * 3 + 1];
        float wz = w[tid * 3 + 2];
        float cx, sx, cy, sy, cz, sz;
        sincosf(0.5f * wx, &sx, &cx);
        sincosf(0.5f * wy, &sy, &cy);
        sincosf(0.5f * wz, &sz, &cz);
        // Ry(wy)*Rx(wx)
        float2 m00 = make_float2(cy * cx,  sy * sx);
        float2 m01 = make_float2(-sy * cx, -cy * sx);
        float2 m10 = make_float2(sy * cx,  -cy * sx);
        float2 m11 = make_float2(cy * cx,  -sy * sx);
        // Rz(wz) on rows
        float2 e0 = make_float2(cz, -sz);
        float2 e1 = make_float2(cz,  sz);
        sg[tid][0] = cmul(e0, m00);
        sg[tid][1] = cmul(e0, m01);
        sg[tid][2] = cmul(e1, m10);
        sg[tid][3] = cmul(e1, m11);
    }
    __syncthreads();

    // Layer matrices: 1024 elements, 4 per thread
#pragma unroll
    for (int r = 0; r < 4; r++) {
        int e = tid + 256 * r;
        int h = e >> 8;
        int st = e & 255;
        int s = st >> 4, t = st & 15;
        float2 prod = make_float2(1.f, 0.f);
#pragma unroll
        for (int q = 0; q < NQ; q++) {
            int sb = (s >> (3 - q)) & 1;
            int tb = (t >> (3 - q)) & 1;
            prod = cmul(prod, sg[h * 4 + q][sb * 2 + tb]);
        }
        bool neg = (((s & 12) == 12) ^ ((s & 3) == 3)) ^ ((s & 6) == 6);
        if (neg) { prod.x = -prod.x; prod.y = -prod.y; }
        sM[h][s][t] = prod;
    }
    __syncthreads();

    {
        int s = tid >> 4, t = tid & 15;
        float2 a1 = make_float2(0.f, 0.f);
        float2 a2 = make_float2(0.f, 0.f);
#pragma unroll
        for (int k = 0; k < DIM; k++) {
            a1 = cadd(a1, cmul(sM[1][s][k], sM[0][k][t]));
            a2 = cadd(a2, cmul(sM[3][s][k], sM[2][k][t]));
        }
        sT[0][s][t] = a1;
        sT[1][s][t] = a2;
    }
    __syncthreads();

    {
        int s = tid >> 4, t = tid & 15;
        float2 u = make_float2(0.f, 0.f);
#pragma unroll
        for (int k = 0; k < DIM; k++)
            u = cadd(u, cmul(sT[1][s][k], sT[0][k][t]));
        ulonglong2 pkd;
        pkd.x = pk2(u.x, u.x);
        pkd.y = pk2(-u.y, u.y);
        g_Upk[t * DIM + s] = pkd;   // column-major [k][s]
    }
}

// ---------------------------------------------------------------------------
// Kernel 2: two patches per thread, Enc (ab/cd) parked in lane-interleaved
// shared memory to cut register pressure, FFMA2 matvec, MUFU sincos.
// ---------------------------------------------------------------------------
#define NT 128

// sEnc slot layout per thread: patch0 ab[0..3] -> 0..3, cd[0..3] -> 4..7,
//                              patch1 ab -> 8..11, cd -> 12..15.
__device__ __forceinline__ void encode(const float* __restrict__ x, int idx,
                                       float2 (*sEnc)[NT], int slot0, int tid) {
    int b  = idx / Pc;
    int p  = idx - b * Pc;
    int ph = p / PWc;
    int pw = p - ph * PWc;

    float  cth[NQ];
    float2 eph[NQ];
#pragma unroll
    for (int n = 0; n < NQ; n++) {
        int dy = n >> 1, dx = n & 1;
        const float* px = x + ((((b * Hc) + (ph + dy)) * Wc + (pw + dx)) * 3);
        float l1 = px[1];
        float l2 = px[2];
        float sb, cb, sp, cp;
        __sincosf(1.57079632679489662f * l1, &sb, &cb);
        __sincosf(3.14159265358979323f * l2, &sp, &cp);
        cth[n] = cb;
        eph[n] = make_float2(sb * cp, sb * sp);
    }
    sEnc[slot0 + 0][tid] = make_float2(cth[0] * cth[1], 0.f);
    sEnc[slot0 + 1][tid] = make_float2(cth[0] * eph[1].x, cth[0] * eph[1].y);
    sEnc[slot0 + 2][tid] = make_float2(eph[0].x * cth[1], eph[0].y * cth[1]);
    sEnc[slot0 + 3][tid] = cmul(eph[0], eph[1]);
    sEnc[slot0 + 4][tid] = make_float2(cth[2] * cth[3], 0.f);
    sEnc[slot0 + 5][tid] = make_float2(cth[2] * eph[3].x, cth[2] * eph[3].y);
    sEnc[slot0 + 6][tid] = make_float2(eph[2].x * cth[3], eph[2].y * cth[3]);
    sEnc[slot0 + 7][tid] = cmul(eph[2], eph[3]);
}

__device__ __forceinline__ void finish(const ull* __restrict__ A,
                                       float* __restrict__ out, int idx) {
    float pr[DIM];
#pragma unroll
    for (int s = 0; s < DIM; s++) {
        ull sq = ffma2(A[s], A[s], 0ull);   // (ar^2, ai^2)
        float a, b2;
        upk2(sq, a, b2);
        pr[s] = a + b2;
    }
    float e1[8], o1[8];
#pragma unroll
    for (int t = 0; t < 8; t++) { e1[t] = pr[2*t] + pr[2*t+1]; o1[t] = pr[2*t] - pr[2*t+1]; }
    float z3 = ((o1[0]+o1[1]) + (o1[2]+o1[3])) + ((o1[4]+o1[5]) + (o1[6]+o1[7]));
    float e2[4], o2[4];
#pragma unroll
    for (int t = 0; t < 4; t++) { e2[t] = e1[2*t] + e1[2*t+1]; o2[t] = e1[2*t] - e1[2*t+1]; }
    float z2 = (o2[0]+o2[1]) + (o2[2]+o2[3]);
    float e3[2], o3[2];
#pragma unroll
    for (int t = 0; t < 2; t++) { e3[t] = e2[2*t] + e2[2*t+1]; o3[t] = e2[2*t] - e2[2*t+1]; }
    float z1 = o3[0] + o3[1];
    float z0 = e3[0] - e3[1];

    reinterpret_cast<float4*>(out)[idx] = make_float4(z0, z1, z2, z3);
}

__global__ void __launch_bounds__(NT, 5)
k_qcnn(const float* __restrict__ x, float* __restrict__ out) {
    __shared__ ulonglong2 sU[DIM * DIM];   // [k][s], 4KB
    __shared__ float2 sEnc[16][NT];        // 16KB, lane-interleaved

    int tid = threadIdx.x;
    for (int i = tid; i < DIM * DIM; i += NT) sU[i] = g_Upk[i];
    __syncthreads();

    int t = blockIdx.x * NT + tid;
    if (t >= HALFc) return;
    int idx0 = t;
    int idx1 = t + HALFc;

    encode(x, idx0, sEnc, 0, tid);
    encode(x, idx1, sEnc, 8, tid);

    ull A0[DIM], A1[DIM];
#pragma unroll
    for (int s = 0; s < DIM; s++) { A0[s] = 0ull; A1[s] = 0ull; }

#pragma unroll
    for (int i = 0; i < 4; i++) {
        float2 ab0 = sEnc[i][tid];
        float2 ab1 = sEnc[8 + i][tid];
#pragma unroll
        for (int j = 0; j < 4; j++) {
            float2 cd0 = sEnc[4 + j][tid];
            float2 cd1 = sEnc[12 + j][tid];
            float2 p0 = cmul(ab0, cd0);
            float2 p1 = cmul(ab1, cd1);
            ull P0 = pk2(p0.x, p0.y), Q0 = pk2(p0.y, p0.x);
            ull P1 = pk2(p1.x, p1.y), Q1 = pk2(p1.y, p1.x);
            const ulonglong2* row = &sU[(i * 4 + j) * DIM];
#pragma unroll
            for (int s = 0; s < DIM; s++) {
                ulonglong2 u = row[s];           // (re,re), (-im,im)
                A0[s] = ffma2(u.x, P0, A0[s]);
                A0[s] = ffma2(u.y, Q0, A0[s]);
                A1[s] = ffma2(u.x, P1, A1[s]);
                A1[s] = ffma2(u.y, Q1, A1[s]);
            }
        }
    }

    finish(A0, out, idx0);
    finish(A1, out, idx1);
}

extern "C" void kernel_launch(void* const* d_in, const int* in_sizes, int n_in,
                              void* d_out, int out_size) {
    const float* x = (const float*)d_in[0];
    const float* w = (const float*)d_in[1];
    float* out = (float*)d_out;

    k_build_U<<<1, 256>>>(w);

    int blocks = (HALFc + NT - 1) / NT;   // 2017
    k_qcnn<<<blocks, NT>>>(x, out);
}

// round 7
// speedup vs baseline: 1.1101x; 1.1101x over previous
#include <cuda_runtime.h>

// QCNN_58025008169535
// x: [32,128,128,3] f32, w: [4,4,3] f32 -> out: [32, 127*127, 4] f32

#define DIM 16
#define NL 4
#define NQ 4

static constexpr int Bc = 32, Hc = 128, Wc = 128;
static constexpr int PHc = Hc - 1, PWc = Wc - 1;
static constexpr int Pc = PHc * PWc;          // 16129
static constexpr int TOTALc = Bc * Pc;        // 516128
static constexpr int HALFc = TOTALc / 2;      // 258064

typedef unsigned long long ull;

// Packed U, column-major [k][s]: (re,re) and (-im,im) of U[s][k]
__device__ ulonglong2 g_Upk[DIM * DIM];

__device__ __forceinline__ float2 cmul(float2 a, float2 b) {
    return make_float2(fmaf(a.x, b.x, -a.y * b.y), fmaf(a.x, b.y, a.y * b.x));
}
__device__ __forceinline__ float2 cadd(float2 a, float2 b) {
    return make_float2(a.x + b.x, a.y + b.y);
}
__device__ __forceinline__ ull pk2(float lo, float hi) {
    ull r; asm("mov.b64 %0, {%1,%2};" : "=l"(r) : "f"(lo), "f"(hi)); return r;
}
__device__ __forceinline__ void upk2(ull v, float& lo, float& hi) {
    asm("mov.b64 {%0,%1}, %2;" : "=f"(lo), "=f"(hi) : "l"(v));
}
__device__ __forceinline__ ull ffma2(ull a, ull b, ull c) {
    ull d; asm("fma.rn.f32x2 %0, %1, %2, %3;" : "=l"(d) : "l"(a), "l"(b), "l"(c));
    return d;
}

// ---------------------------------------------------------------------------
// Kernel 1 (256 threads): build the variational unitary in parallel.
// ---------------------------------------------------------------------------
__global__ void k_build_U(const float* __restrict__ w) {
    __shared__ float2 sg[16][4];
    __shared__ float2 sM[4][DIM][DIM];
    __shared__ float2 sT[2][DIM][DIM];

    int tid = threadIdx.x;

    if (tid < 16) {
        float wx = w[tid * 3 + 0];
        float wy = w[tid * 3 + 1];
        float wz = w[tid * 3 + 2];
        float cx, sx, cy, sy, cz, sz;
        sincosf(0.5f * wx, &sx, &cx);
        sincosf(0.5f * wy, &sy, &cy);
        sincosf(0.5f * wz, &sz, &cz);
        float2 m00 = make_float2(cy * cx,  sy * sx);
        float2 m01 = make_float2(-sy * cx, -cy * sx);
        float2 m10 = make_float2(sy * cx,  -cy * sx);
        float2 m11 = make_float2(cy * cx,  -sy * sx);
        float2 e0 = make_float2(cz, -sz);
        float2 e1 = make_float2(cz,  sz);
        sg[tid][0] = cmul(e0, m00);
        sg[tid][1] = cmul(e0, m01);
        sg[tid][2] = cmul(e1, m10);
        sg[tid][3] = cmul(e1, m11);
    }
    __syncthreads();

#pragma unroll
    for (int r = 0; r < 4; r++) {
        int e = tid + 256 * r;
        int h = e >> 8;
        int st = e & 255;
        int s = st >> 4, t = st & 15;
        float2 prod = make_float2(1.f, 0.f);
#pragma unroll
        for (int q = 0; q < NQ; q++) {
            int sb = (s >> (3 - q)) & 1;
            int tb = (t >> (3 - q)) & 1;
            prod = cmul(prod, sg[h * 4 + q][sb * 2 + tb]);
        }
        bool neg = (((s & 12) == 12) ^ ((s & 3) == 3)) ^ ((s & 6) == 6);
        if (neg) { prod.x = -prod.x; prod.y = -prod.y; }
        sM[h][s][t] = prod;
    }
    __syncthreads();

    {
        int s = tid >> 4, t = tid & 15;
        float2 a1 = make_float2(0.f, 0.f);
        float2 a2 = make_float2(0.f, 0.f);
#pragma unroll
        for (int k = 0; k < DIM; k++) {
            a1 = cadd(a1, cmul(sM[1][s][k], sM[0][k][t]));
            a2 = cadd(a2, cmul(sM[3][s][k], sM[2][k][t]));
        }
        sT[0][s][t] = a1;
        sT[1][s][t] = a2;
    }
    __syncthreads();

    {
        int s = tid >> 4, t = tid & 15;
        float2 u = make_float2(0.f, 0.f);
#pragma unroll
        for (int k = 0; k < DIM; k++)
            u = cadd(u, cmul(sT[1][s][k], sT[0][k][t]));
        ulonglong2 pkd;
        pkd.x = pk2(u.x, u.x);
        pkd.y = pk2(-u.y, u.y);
        g_Upk[t * DIM + s] = pkd;   // column-major [k][s]
    }
}

// ---------------------------------------------------------------------------
// Kernel 2: warp-parity state split. Even warps: states 0-7, odd warps:
// states 8-15, lane-matched pairs handle the same two patches. A regs
// halved, U smem traffic per patch halved, everything else in registers.
// ---------------------------------------------------------------------------
#define NT 128

struct Enc { float2 ab[4]; float2 cd[4]; };

__device__ __forceinline__ void encode(const float* __restrict__ x, int idx, Enc& e) {
    int b  = idx / Pc;
    int p  = idx - b * Pc;
    int ph = p / PWc;
    int pw = p - ph * PWc;

    float  cth[NQ];
    float2 eph[NQ];
#pragma unroll
    for (int n = 0; n < NQ; n++) {
        int dy = n >> 1, dx = n & 1;
        const float* px = x + ((((b * Hc) + (ph + dy)) * Wc + (pw + dx)) * 3);
        float l1 = px[1];
        float l2 = px[2];
        float sb, cb, sp, cp;
        __sincosf(1.57079632679489662f * l1, &sb, &cb);
        __sincosf(3.14159265358979323f * l2, &sp, &cp);
        cth[n] = cb;
        eph[n] = make_float2(sb * cp, sb * sp);
    }
    e.ab[0] = make_float2(cth[0] * cth[1], 0.f);
    e.ab[1] = make_float2(cth[0] * eph[1].x, cth[0] * eph[1].y);
    e.ab[2] = make_float2(eph[0].x * cth[1], eph[0].y * cth[1]);
    e.ab[3] = cmul(eph[0], eph[1]);
    e.cd[0] = make_float2(cth[2] * cth[3], 0.f);
    e.cd[1] = make_float2(cth[2] * eph[3].x, cth[2] * eph[3].y);
    e.cd[2] = make_float2(eph[2].x * cth[3], eph[2].y * cth[3]);
    e.cd[3] = cmul(eph[2], eph[3]);
}

// Partial Walsh over 8 probabilities (states h*8 + 0..7):
// w0 = plain sum, w1 = sign by bit2, w2 = bit1, w3 = bit0.
__device__ __forceinline__ float4 walsh8(const float* pr) {
    float e1[4], o1[4];
#pragma unroll
    for (int t = 0; t < 4; t++) { e1[t] = pr[2*t] + pr[2*t+1]; o1[t] = pr[2*t] - pr[2*t+1]; }
    float w3 = (o1[0] + o1[1]) + (o1[2] + o1[3]);
    float e2[2], o2[2];
#pragma unroll
    for (int t = 0; t < 2; t++) { e2[t] = e1[2*t] + e1[2*t+1]; o2[t] = e1[2*t] - e1[2*t+1]; }
    float w2 = o2[0] + o2[1];
    float w1 = e2[0] - e2[1];
    float w0 = e2[0] + e2[1];
    return make_float4(w0, w1, w2, w3);
}

__global__ void __launch_bounds__(NT, 5)
k_qcnn(const float* __restrict__ x, float* __restrict__ out) {
    __shared__ ulonglong2 sU[DIM * DIM];   // [k][s], 4KB
    __shared__ float4 sP0[NT];             // patch0 Walsh partials
    __shared__ float4 sP1[NT];             // patch1 Walsh partials

    int tid = threadIdx.x;
    for (int i = tid; i < DIM * DIM; i += NT) sU[i] = g_Upk[i];
    __syncthreads();

    int wrp  = tid >> 5;
    int lane = tid & 31;
    int h    = wrp & 1;                    // state half: warp-uniform
    int pairpos = (wrp >> 1) * 32 + lane;  // 0..63 within block

    int g = blockIdx.x * (NT / 2) + pairpos;
    bool active = (g < HALFc);
    int idx0 = g;
    int idx1 = g + HALFc;

    float4 f0 = make_float4(0.f, 0.f, 0.f, 0.f);
    float4 f1 = f0;

    if (active) {
        Enc e0, e1;
        encode(x, idx0, e0);
        encode(x, idx1, e1);

        ull A0[8], A1[8];
#pragma unroll
        for (int s = 0; s < 8; s++) { A0[s] = 0ull; A1[s] = 0ull; }

        const ulonglong2* ubase = sU + h * 8;
#pragma unroll
        for (int i = 0; i < 4; i++) {
#pragma unroll
            for (int j = 0; j < 4; j++) {
                float2 p0 = cmul(e0.ab[i], e0.cd[j]);
                float2 p1 = cmul(e1.ab[i], e1.cd[j]);
                ull P0 = pk2(p0.x, p0.y), Q0 = pk2(p0.y, p0.x);
                ull P1 = pk2(p1.x, p1.y), Q1 = pk2(p1.y, p1.x);
                const ulonglong2* row = ubase + (i * 4 + j) * DIM;
#pragma unroll
                for (int s = 0; s < 8; s++) {
                    ulonglong2 u = row[s];           // (re,re), (-im,im)
                    A0[s] = ffma2(u.x, P0, A0[s]);
                    A1[s] = ffma2(u.x, P1, A1[s]);
                    A0[s] = ffma2(u.y, Q0, A0[s]);
                    A1[s] = ffma2(u.y, Q1, A1[s]);
                }
            }
        }

        float pr0[8], pr1[8];
#pragma unroll
        for (int s = 0; s < 8; s++) {
            ull q0 = ffma2(A0[s], A0[s], 0ull);
            ull q1 = ffma2(A1[s], A1[s], 0ull);
            float a, b;
            upk2(q0, a, b); pr0[s] = a + b;
            upk2(q1, a, b); pr1[s] = a + b;
        }
        f0 = walsh8(pr0);
        f1 = walsh8(pr1);
    }

    sP0[tid] = f0;
    sP1[tid] = f1;
    __syncthreads();

    if (active) {
        if (h == 0) {
            // combine patch0: own = half0, partner (tid+32) = half1
            float4 q = sP0[tid + 32];
            reinterpret_cast<float4*>(out)[idx0] =
                make_float4(f0.x - q.x, f0.y + q.y, f0.z + q.z, f0.w + q.w);
        } else {
            // combine patch1: partner (tid-32) = half0, own = half1
            float4 q = sP1[tid - 32];
            reinterpret_cast<float4*>(out)[idx1] =
                make_float4(q.x - f1.x, q.y + f1.y, q.z + f1.z, q.w + f1.w);
        }
    }
}

extern "C" void kernel_launch(void* const* d_in, const int* in_sizes, int n_in,
                              void* d_out, int out_size) {
    const float* x = (const float*)d_in[0];
    const float* w = (const float*)d_in[1];
    float* out = (float*)d_out;

    k_build_U<<<1, 256>>>(w);

    int blocks = (HALFc + (NT / 2) - 1) / (NT / 2);   // 4033
    k_qcnn<<<blocks, NT>>>(x, out);
}